// round 3
// baseline (speedup 1.0000x reference)
#include <cuda_runtime.h>

#define D 64
#define MAXN 150016
#define MAXNNZ 2500000
typedef unsigned long long ull;

// Scratch in device globals (no dynamic allocation allowed).
__device__ __align__(16) float g_ego_a[MAXN * D];      // 38.4 MB (L2-resident)
__device__ __align__(16) float g_ego_b[MAXN * D];      // 38.4 MB
__device__ __align__(16) float g_final[MAXN * D * 4];  // 153.6 MB concat buffer
__device__ __align__(16) int2  g_edge[MAXNNZ];         // CSR (col, val) pairs
__device__ int g_hist[MAXN];
__device__ int g_rowptr[MAXN + 1];
__device__ int g_cursor[MAXN];
__device__ int g_partial[1024];

__device__ __forceinline__ float lrelu(float x) { return x >= 0.f ? x : 0.2f * x; }

__device__ __forceinline__ ull ffma2(ull a, ull b, ull c) {
    ull d;
    asm("fma.rn.f32x2 %0, %1, %2, %3;" : "=l"(d) : "l"(a), "l"(b), "l"(c));
    return d;
}

union f2u { float2 f; ull u; };

// ---------------------------------------------------------------------------
// init: ego_a = concat(user,item); final[:,0:64] = ego; hist = 0 + edge count
// (one histogram atomic per thread: nnz ~= n*16, same grid)
// ---------------------------------------------------------------------------
__global__ __launch_bounds__(256) void init_kernel(const float4* __restrict__ user,
                                                   const float4* __restrict__ item,
                                                   const int* __restrict__ rows,
                                                   int n_users, int n_nodes, int nnz) {
    int idx = blockIdx.x * 256 + threadIdx.x;
    if (idx < n_nodes * 16) {
        int n = idx >> 4, c = idx & 15;
        float4 v = (n < n_users) ? __ldg(user + n * 16 + c)
                                 : __ldg(item + (n - n_users) * 16 + c);
        ((float4*)g_ego_a)[idx] = v;
        ((float4*)g_final)[n * 64 + c] = v;
        if (c == 0) g_hist[n] = 0;
    }
}

__global__ __launch_bounds__(256) void count_kernel(const int* __restrict__ rows, int nnz) {
    int e = blockIdx.x * 256 + threadIdx.x;
    if (e < nnz) atomicAdd(&g_hist[__ldg(rows + e)], 1);
}

__global__ __launch_bounds__(256) void scan1_kernel(int n) {
    __shared__ int wsum[8];
    int i = blockIdx.x * 256 + threadIdx.x;
    int lane = threadIdx.x & 31, w = threadIdx.x >> 5;
    int v = (i < n) ? g_hist[i] : 0;
    int x = v;
#pragma unroll
    for (int off = 1; off < 32; off <<= 1) {
        int y = __shfl_up_sync(0xffffffffu, x, off);
        if (lane >= off) x += y;
    }
    if (lane == 31) wsum[w] = x;
    __syncthreads();
    if (threadIdx.x == 0) {
        int run = 0;
#pragma unroll
        for (int q = 0; q < 8; q++) { int t = wsum[q]; wsum[q] = run; run += t; }
        g_partial[blockIdx.x] = run;
    }
    __syncthreads();
    if (i < n) g_rowptr[i] = x - v + wsum[w];
}

__global__ __launch_bounds__(1024) void scan2_kernel(int nblocks) {
    __shared__ int sh[1024];
    int t = threadIdx.x;
    int v = (t < nblocks) ? g_partial[t] : 0;
    sh[t] = v;
    __syncthreads();
#pragma unroll
    for (int off = 1; off < 1024; off <<= 1) {
        int add = (t >= off) ? sh[t - off] : 0;
        __syncthreads();
        sh[t] += add;
        __syncthreads();
    }
    if (t < nblocks) g_partial[t] = sh[t] - v;  // exclusive
}

__global__ __launch_bounds__(256) void finalize_kernel(int n, int nnz) {
    int i = blockIdx.x * 256 + threadIdx.x;
    if (i < n) {
        int off = g_rowptr[i] + g_partial[i >> 8];
        g_rowptr[i] = off;
        g_cursor[i] = off;
    }
    if (i == 0) g_rowptr[n] = nnz;
}

__global__ __launch_bounds__(256) void scatter_kernel(const float* __restrict__ vals,
                                                      const int* __restrict__ rows,
                                                      const int* __restrict__ cols,
                                                      int nnz) {
    int e = blockIdx.x * 256 + threadIdx.x;
    if (e >= nnz) return;
    int r = __ldg(rows + e);
    int pos = atomicAdd(&g_cursor[r], 1);
    g_edge[pos] = make_int2(__ldg(cols + e), __float_as_int(__ldg(vals + e)));
}

// ---------------------------------------------------------------------------
// fused layer: CSR spmm (warp/row, gather from ego_in) straight into SD/PD
// smem tiles, then f32x2 GEMM transform:
//   ego_out = lrelu(side@Wgc+bg) + lrelu((ego_in*side)@Wbi+bb)
//   final slice = normalize(ego_out)
// 64-node tile, 256 threads, 100KB smem, 2 blocks/SM.
// ---------------------------------------------------------------------------
#define RPITCH 66  // float2 units per k-row (even => 16B alignment at even k)
#define TSMEM (2 * 64 * RPITCH * 8 + 2 * 4096 * 4)  // 100352 bytes

__global__ __launch_bounds__(256, 2) void layer_kernel(const float4* __restrict__ Wgc,
                                                       const float* __restrict__ bgc,
                                                       const float4* __restrict__ Wbi,
                                                       const float* __restrict__ bbi,
                                                       int n_nodes, int layer) {
    extern __shared__ char shraw[];
    float2* SD = (float2*)shraw;               // [64 rows][64 k] duplicated (s,s)
    float2* PD = SD + 64 * RPITCH;             // duplicated (p,p)
    float*  Wg = (float*)(PD + 64 * RPITCH);   // [64 k][64 c]
    float*  Wb = Wg + 4096;

    const float4* __restrict__ ein  = (layer & 1) ? (const float4*)g_ego_b
                                                  : (const float4*)g_ego_a;
    float4* __restrict__ eout = (layer & 1) ? (float4*)g_ego_a : (float4*)g_ego_b;

    int tid = threadIdx.x;
    int base = blockIdx.x * 64;

    // weights -> smem (issued first; overlaps the gather loop's latency)
    for (int i = tid; i < 1024; i += 256) {
        ((float4*)Wg)[i] = __ldg(Wgc + i);
        ((float4*)Wb)[i] = __ldg(Wbi + i);
    }

    // Phase 1: spmm. One warp per row, 16 lanes x float4 cover D=64,
    // halves process alternating edges, shfl-combine, write SD/PD.
    int warp = tid >> 5, lane = tid & 31;
    int half = lane >> 4, c = lane & 15;
    for (int rr = warp; rr < 64; rr += 8) {
        int row = base + rr;
        float4 acc = make_float4(0.f, 0.f, 0.f, 0.f);
        float4 e4 = acc;
        if (row < n_nodes) {
            int s = __ldg(&g_rowptr[row]);
            int e = __ldg(&g_rowptr[row + 1]);
            for (int p = s + half; p < e; p += 2) {
                int2 ed = __ldg(&g_edge[p]);
                float v = __int_as_float(ed.y);
                float4 x = __ldg(ein + ed.x * 16 + c);
                acc.x += v * x.x; acc.y += v * x.y;
                acc.z += v * x.z; acc.w += v * x.w;
            }
            e4 = __ldg(ein + row * 16 + c);
        }
        acc.x += __shfl_xor_sync(0xffffffffu, acc.x, 16);
        acc.y += __shfl_xor_sync(0xffffffffu, acc.y, 16);
        acc.z += __shfl_xor_sync(0xffffffffu, acc.z, 16);
        acc.w += __shfl_xor_sync(0xffffffffu, acc.w, 16);
        if (half == 0) {
            float2* sd = &SD[rr * RPITCH + c * 4];
            sd[0] = make_float2(acc.x, acc.x);
            sd[1] = make_float2(acc.y, acc.y);
            sd[2] = make_float2(acc.z, acc.z);
            sd[3] = make_float2(acc.w, acc.w);
        } else {
            float2* pd = &PD[rr * RPITCH + c * 4];
            float px = acc.x * e4.x, py = acc.y * e4.y;
            float pz = acc.z * e4.z, pw = acc.w * e4.w;
            pd[0] = make_float2(px, px);
            pd[1] = make_float2(py, py);
            pd[2] = make_float2(pz, pz);
            pd[3] = make_float2(pw, pw);
        }
    }
    __syncthreads();

    // Phase 2: dual GEMM, 4x4 per thread, f32x2 packed FMA.
    int r0 = (tid >> 4) * 4;   // node sub-rows
    int c0 = (tid & 15) * 4;   // output cols

    ull ag[4][2] = {}, ab[4][2] = {};

#pragma unroll 4
    for (int k = 0; k < 64; k += 2) {
        ulonglong2 wg0 = *(const ulonglong2*)&Wg[k * 64 + c0];
        ulonglong2 wg1 = *(const ulonglong2*)&Wg[(k + 1) * 64 + c0];
        ulonglong2 wb0 = *(const ulonglong2*)&Wb[k * 64 + c0];
        ulonglong2 wb1 = *(const ulonglong2*)&Wb[(k + 1) * 64 + c0];
#pragma unroll
        for (int i = 0; i < 4; i++) {
            ulonglong2 sd = *(const ulonglong2*)&SD[(r0 + i) * RPITCH + k];
            ulonglong2 pd = *(const ulonglong2*)&PD[(r0 + i) * RPITCH + k];
            ag[i][0] = ffma2(sd.x, wg0.x, ag[i][0]);
            ag[i][1] = ffma2(sd.x, wg0.y, ag[i][1]);
            ag[i][0] = ffma2(sd.y, wg1.x, ag[i][0]);
            ag[i][1] = ffma2(sd.y, wg1.y, ag[i][1]);
            ab[i][0] = ffma2(pd.x, wb0.x, ab[i][0]);
            ab[i][1] = ffma2(pd.x, wb0.y, ab[i][1]);
            ab[i][0] = ffma2(pd.y, wb1.x, ab[i][0]);
            ab[i][1] = ffma2(pd.y, wb1.y, ab[i][1]);
        }
    }

    float4 bg4 = __ldg((const float4*)bgc + (c0 >> 2));
    float4 bb4 = __ldg((const float4*)bbi + (c0 >> 2));

    float v[4][4];
    float ssq[4];
#pragma unroll
    for (int i = 0; i < 4; i++) {
        f2u a0, a1, b0, b1;
        a0.u = ag[i][0]; a1.u = ag[i][1];
        b0.u = ab[i][0]; b1.u = ab[i][1];
        v[i][0] = lrelu(a0.f.x + bg4.x) + lrelu(b0.f.x + bb4.x);
        v[i][1] = lrelu(a0.f.y + bg4.y) + lrelu(b0.f.y + bb4.y);
        v[i][2] = lrelu(a1.f.x + bg4.z) + lrelu(b1.f.x + bb4.z);
        v[i][3] = lrelu(a1.f.y + bg4.w) + lrelu(b1.f.y + bb4.w);
        ssq[i] = v[i][0] * v[i][0] + v[i][1] * v[i][1] + v[i][2] * v[i][2] + v[i][3] * v[i][3];
    }
    // reduce ssq across the 16 threads (lanes tid&15) sharing the same rows
#pragma unroll
    for (int off = 1; off < 16; off <<= 1) {
#pragma unroll
        for (int i = 0; i < 4; i++)
            ssq[i] += __shfl_xor_sync(0xffffffffu, ssq[i], off);
    }
#pragma unroll
    for (int i = 0; i < 4; i++) {
        int node = base + r0 + i;
        if (node < n_nodes) {
            float inv = 1.0f / fmaxf(sqrtf(ssq[i]), 1e-12f);
            float4 raw = make_float4(v[i][0], v[i][1], v[i][2], v[i][3]);
            eout[node * 16 + (c0 >> 2)] = raw;  // raw carries forward
            float4 nn = make_float4(raw.x * inv, raw.y * inv, raw.z * inv, raw.w * inv);
            ((float4*)g_final)[node * 64 + (layer + 1) * 16 + (c0 >> 2)] = nn;
        }
    }
}

// ---------------------------------------------------------------------------
// gather: out = [final[u] | final[nu+i] | final[nu+j]]
// ---------------------------------------------------------------------------
__global__ __launch_bounds__(256) void gather_kernel(const int* __restrict__ u,
                                                     const int* __restrict__ ii,
                                                     const int* __restrict__ jj,
                                                     int n_users, int B,
                                                     float4* __restrict__ out) {
    int idx = blockIdx.x * 256 + threadIdx.x;
    int total = 3 * B * 64;
    if (idx >= total) return;
    int c = idx & 63;
    int t = idx >> 6;
    int b = t % B;
    int sel = t / B;
    int row = (sel == 0) ? __ldg(u + b)
            : (sel == 1) ? (n_users + __ldg(ii + b))
                         : (n_users + __ldg(jj + b));
    out[idx] = ((const float4*)g_final)[row * 64 + c];
}

// ---------------------------------------------------------------------------
extern "C" void kernel_launch(void* const* d_in, const int* in_sizes, int n_in,
                              void* d_out, int out_size) {
    const float* user = (const float*)d_in[0];
    const float* item = (const float*)d_in[1];
    const float* Wgc  = (const float*)d_in[2];
    const float* bgc  = (const float*)d_in[3];
    const float* Wbi  = (const float*)d_in[4];
    const float* bbi  = (const float*)d_in[5];
    const float* vals = (const float*)d_in[6];
    const int*   rows = (const int*)d_in[7];
    const int*   cols = (const int*)d_in[8];
    const int*   u    = (const int*)d_in[9];
    const int*   ii   = (const int*)d_in[10];
    const int*   jj   = (const int*)d_in[11];

    int n_users = in_sizes[0] / D;
    int n_items = in_sizes[1] / D;
    int n = n_users + n_items;
    int nnz = in_sizes[6];
    int L = in_sizes[2] / (D * D);
    int B = in_sizes[9];

    cudaFuncSetAttribute(layer_kernel,
                         cudaFuncAttributeMaxDynamicSharedMemorySize, TSMEM);

    int eb = (nnz + 255) / 256;
    int nb = (n + 255) / 256;
    init_kernel<<<(n * 16 + 255) / 256, 256>>>((const float4*)user, (const float4*)item,
                                               rows, n_users, n, nnz);
    count_kernel<<<eb, 256>>>(rows, nnz);
    scan1_kernel<<<nb, 256>>>(n);
    scan2_kernel<<<1, 1024>>>(nb);
    finalize_kernel<<<nb, 256>>>(n, nnz);
    scatter_kernel<<<eb, 256>>>(vals, rows, cols, nnz);

    for (int l = 0; l < L; l++) {
        layer_kernel<<<(n + 63) / 64, 256, TSMEM>>>(
            (const float4*)(Wgc + l * D * D), bgc + l * D,
            (const float4*)(Wbi + l * D * D), bbi + l * D, n, l);
    }
    gather_kernel<<<(3 * B * 64 + 255) / 256, 256>>>(u, ii, jj, n_users, B, (float4*)d_out);
}

// round 4
// speedup vs baseline: 1.9089x; 1.9089x over previous
#include <cuda_runtime.h>

#define D 64
#define MAXN 150016
#define MAXNNZ 2500000
typedef unsigned long long ull;

// Scratch in device globals (no dynamic allocation allowed).
__device__ __align__(16) float g_ego[MAXN * D];        // 38.4 MB, L2-resident
__device__ __align__(16) float g_side[MAXN * D];       // 38.4 MB, L2-resident
__device__ __align__(16) float g_final[MAXN * D * 4];  // 153.6 MB concat buffer
__device__ __align__(16) int2  g_edge[MAXNNZ];         // CSR (col, val) pairs
__device__ int g_hist[MAXN];
__device__ int g_rowptr[MAXN + 1];
__device__ int g_cursor[MAXN];
__device__ int g_partial[1024];

__device__ __forceinline__ float lrelu(float x) { return x >= 0.f ? x : 0.2f * x; }

__device__ __forceinline__ ull ffma2(ull a, ull b, ull c) {
    ull d;
    asm("fma.rn.f32x2 %0, %1, %2, %3;" : "=l"(d) : "l"(a), "l"(b), "l"(c));
    return d;
}

union f2u { float2 f; ull u; };

// ---------------------------------------------------------------------------
// init: ego = concat(user,item); final[:,0:64] = ego; hist = 0
// ---------------------------------------------------------------------------
__global__ __launch_bounds__(256) void init_kernel(const float4* __restrict__ user,
                                                   const float4* __restrict__ item,
                                                   int n_users, int n_nodes) {
    int idx = blockIdx.x * 256 + threadIdx.x;
    if (idx >= n_nodes * 16) return;
    int n = idx >> 4, c = idx & 15;
    float4 v = (n < n_users) ? __ldg(user + n * 16 + c)
                             : __ldg(item + (n - n_users) * 16 + c);
    ((float4*)g_ego)[idx] = v;
    ((float4*)g_final)[n * 64 + c] = v;
    if (c == 0) g_hist[n] = 0;
}

// ---------------------------------------------------------------------------
// CSR build: count -> scan (3 stages) -> scatter
// ---------------------------------------------------------------------------
__global__ __launch_bounds__(256) void count_kernel(const int* __restrict__ rows, int nnz) {
    int e = blockIdx.x * 256 + threadIdx.x;
    if (e < nnz) atomicAdd(&g_hist[__ldg(rows + e)], 1);
}

__global__ __launch_bounds__(256) void scan1_kernel(int n) {
    __shared__ int wsum[8];
    int i = blockIdx.x * 256 + threadIdx.x;
    int lane = threadIdx.x & 31, w = threadIdx.x >> 5;
    int v = (i < n) ? g_hist[i] : 0;
    int x = v;
#pragma unroll
    for (int off = 1; off < 32; off <<= 1) {
        int y = __shfl_up_sync(0xffffffffu, x, off);
        if (lane >= off) x += y;
    }
    if (lane == 31) wsum[w] = x;
    __syncthreads();
    if (threadIdx.x == 0) {
        int run = 0;
#pragma unroll
        for (int q = 0; q < 8; q++) { int t = wsum[q]; wsum[q] = run; run += t; }
        g_partial[blockIdx.x] = run;
    }
    __syncthreads();
    if (i < n) g_rowptr[i] = x - v + wsum[w];
}

__global__ __launch_bounds__(1024) void scan2_kernel(int nblocks) {
    __shared__ int sh[1024];
    int t = threadIdx.x;
    int v = (t < nblocks) ? g_partial[t] : 0;
    sh[t] = v;
    __syncthreads();
#pragma unroll
    for (int off = 1; off < 1024; off <<= 1) {
        int add = (t >= off) ? sh[t - off] : 0;
        __syncthreads();
        sh[t] += add;
        __syncthreads();
    }
    if (t < nblocks) g_partial[t] = sh[t] - v;  // exclusive
}

__global__ __launch_bounds__(256) void finalize_kernel(int n, int nnz) {
    int i = blockIdx.x * 256 + threadIdx.x;
    if (i < n) {
        int off = g_rowptr[i] + g_partial[i >> 8];
        g_rowptr[i] = off;
        g_cursor[i] = off;
    }
    if (i == 0) g_rowptr[n] = nnz;
}

__global__ __launch_bounds__(256) void scatter_kernel(const float* __restrict__ vals,
                                                      const int* __restrict__ rows,
                                                      const int* __restrict__ cols,
                                                      int nnz) {
    int e = blockIdx.x * 256 + threadIdx.x;
    if (e >= nnz) return;
    int r = __ldg(rows + e);
    int pos = atomicAdd(&g_cursor[r], 1);
    g_edge[pos] = make_int2(__ldg(cols + e), __float_as_int(__ldg(vals + e)));
}

// ---------------------------------------------------------------------------
// spmm: 16 threads per row (16 rows / 256-thread block), edge loop unrolled
// x4 with independent accumulators -> 4 ego LDG.128 + 4 edge LDG.64 in
// flight per thread. No atomics; each row written once, coalesced.
// ---------------------------------------------------------------------------
__global__ __launch_bounds__(256) void spmm_csr_kernel(int n) {
    int row = blockIdx.x * 16 + (threadIdx.x >> 4);
    if (row >= n) return;
    int c = threadIdx.x & 15;
    int s = __ldg(&g_rowptr[row]);
    int e = __ldg(&g_rowptr[row + 1]);
    const float4* __restrict__ egos = (const float4*)g_ego;

    float4 a0 = make_float4(0.f, 0.f, 0.f, 0.f);
    float4 a1 = a0, a2 = a0, a3 = a0;
    int p = s;
    for (; p + 4 <= e; p += 4) {
        int2 e0 = __ldg(&g_edge[p]);
        int2 e1 = __ldg(&g_edge[p + 1]);
        int2 e2 = __ldg(&g_edge[p + 2]);
        int2 e3 = __ldg(&g_edge[p + 3]);
        float4 x0 = __ldg(egos + e0.x * 16 + c);
        float4 x1 = __ldg(egos + e1.x * 16 + c);
        float4 x2 = __ldg(egos + e2.x * 16 + c);
        float4 x3 = __ldg(egos + e3.x * 16 + c);
        float v0 = __int_as_float(e0.y), v1 = __int_as_float(e1.y);
        float v2 = __int_as_float(e2.y), v3 = __int_as_float(e3.y);
        a0.x += v0 * x0.x; a0.y += v0 * x0.y; a0.z += v0 * x0.z; a0.w += v0 * x0.w;
        a1.x += v1 * x1.x; a1.y += v1 * x1.y; a1.z += v1 * x1.z; a1.w += v1 * x1.w;
        a2.x += v2 * x2.x; a2.y += v2 * x2.y; a2.z += v2 * x2.z; a2.w += v2 * x2.w;
        a3.x += v3 * x3.x; a3.y += v3 * x3.y; a3.z += v3 * x3.z; a3.w += v3 * x3.w;
    }
    for (; p < e; p++) {
        int2 ed = __ldg(&g_edge[p]);
        float v = __int_as_float(ed.y);
        float4 x = __ldg(egos + ed.x * 16 + c);
        a0.x += v * x.x; a0.y += v * x.y; a0.z += v * x.z; a0.w += v * x.w;
    }
    a0.x += a1.x + a2.x + a3.x;
    a0.y += a1.y + a2.y + a3.y;
    a0.z += a1.z + a2.z + a3.z;
    a0.w += a1.w + a2.w + a3.w;
    ((float4*)g_side)[row * 16 + c] = a0;
}

// ---------------------------------------------------------------------------
// transform: ego_new = lrelu(side@Wgc+bg) + lrelu((ego*side)@Wbi+bb)
//            g_final slice = normalize(ego_new);  ego <- ego_new (raw)
// 64-node tile, 256 threads, 4x4 per thread, f32x2 packed FMA.
// ---------------------------------------------------------------------------
#define RPITCH 66  // float2 units per k-row (even => 16B alignment at even k)
#define TSMEM (2 * 64 * RPITCH * 8 + 2 * 4096 * 4)  // 100352 bytes

__global__ __launch_bounds__(256, 2) void transform_kernel(const float4* __restrict__ Wgc,
                                                           const float* __restrict__ bgc,
                                                           const float4* __restrict__ Wbi,
                                                           const float* __restrict__ bbi,
                                                           int n_nodes, int layer) {
    extern __shared__ char shraw[];
    float2* SD = (float2*)shraw;               // [64 rows][64 k] duplicated (s,s)
    float2* PD = SD + 64 * RPITCH;             // duplicated (p,p)
    float*  Wg = (float*)(PD + 64 * RPITCH);   // [64 k][64 c]
    float*  Wb = Wg + 4096;

    int tid = threadIdx.x;
    int base = blockIdx.x * 64;

    for (int i = tid; i < 1024; i += 256) {
        ((float4*)Wg)[i] = __ldg(Wgc + i);
        ((float4*)Wb)[i] = __ldg(Wbi + i);
        int r = i >> 4, cc = i & 15;
        int node = base + r;
        float4 s4 = make_float4(0.f, 0.f, 0.f, 0.f);
        float4 e4 = s4;
        if (node < n_nodes) {
            s4 = ((const float4*)g_side)[node * 16 + cc];
            e4 = ((const float4*)g_ego)[node * 16 + cc];
        }
        int kb = cc * 4;
        float2* sd = &SD[r * RPITCH + kb];
        float2* pd = &PD[r * RPITCH + kb];
        sd[0] = make_float2(s4.x, s4.x);
        sd[1] = make_float2(s4.y, s4.y);
        sd[2] = make_float2(s4.z, s4.z);
        sd[3] = make_float2(s4.w, s4.w);
        pd[0] = make_float2(s4.x * e4.x, s4.x * e4.x);
        pd[1] = make_float2(s4.y * e4.y, s4.y * e4.y);
        pd[2] = make_float2(s4.z * e4.z, s4.z * e4.z);
        pd[3] = make_float2(s4.w * e4.w, s4.w * e4.w);
    }
    __syncthreads();

    int r0 = (tid >> 4) * 4;   // node sub-rows
    int c0 = (tid & 15) * 4;   // output cols

    ull ag[4][2] = {}, ab[4][2] = {};

#pragma unroll 4
    for (int k = 0; k < 64; k += 2) {
        ulonglong2 wg0 = *(const ulonglong2*)&Wg[k * 64 + c0];
        ulonglong2 wg1 = *(const ulonglong2*)&Wg[(k + 1) * 64 + c0];
        ulonglong2 wb0 = *(const ulonglong2*)&Wb[k * 64 + c0];
        ulonglong2 wb1 = *(const ulonglong2*)&Wb[(k + 1) * 64 + c0];
#pragma unroll
        for (int i = 0; i < 4; i++) {
            ulonglong2 sd = *(const ulonglong2*)&SD[(r0 + i) * RPITCH + k];
            ulonglong2 pd = *(const ulonglong2*)&PD[(r0 + i) * RPITCH + k];
            ag[i][0] = ffma2(sd.x, wg0.x, ag[i][0]);
            ag[i][1] = ffma2(sd.x, wg0.y, ag[i][1]);
            ag[i][0] = ffma2(sd.y, wg1.x, ag[i][0]);
            ag[i][1] = ffma2(sd.y, wg1.y, ag[i][1]);
            ab[i][0] = ffma2(pd.x, wb0.x, ab[i][0]);
            ab[i][1] = ffma2(pd.x, wb0.y, ab[i][1]);
            ab[i][0] = ffma2(pd.y, wb1.x, ab[i][0]);
            ab[i][1] = ffma2(pd.y, wb1.y, ab[i][1]);
        }
    }

    float4 bg4 = __ldg((const float4*)bgc + (c0 >> 2));
    float4 bb4 = __ldg((const float4*)bbi + (c0 >> 2));

    float v[4][4];
    float ssq[4];
#pragma unroll
    for (int i = 0; i < 4; i++) {
        f2u a0, a1, b0, b1;
        a0.u = ag[i][0]; a1.u = ag[i][1];
        b0.u = ab[i][0]; b1.u = ab[i][1];
        v[i][0] = lrelu(a0.f.x + bg4.x) + lrelu(b0.f.x + bb4.x);
        v[i][1] = lrelu(a0.f.y + bg4.y) + lrelu(b0.f.y + bb4.y);
        v[i][2] = lrelu(a1.f.x + bg4.z) + lrelu(b1.f.x + bb4.z);
        v[i][3] = lrelu(a1.f.y + bg4.w) + lrelu(b1.f.y + bb4.w);
        ssq[i] = v[i][0] * v[i][0] + v[i][1] * v[i][1] + v[i][2] * v[i][2] + v[i][3] * v[i][3];
    }
    // reduce ssq across the 16 threads (lanes tid&15) sharing the same rows
#pragma unroll
    for (int off = 1; off < 16; off <<= 1) {
#pragma unroll
        for (int i = 0; i < 4; i++)
            ssq[i] += __shfl_xor_sync(0xffffffffu, ssq[i], off);
    }
#pragma unroll
    for (int i = 0; i < 4; i++) {
        int node = base + r0 + i;
        if (node < n_nodes) {
            float inv = 1.0f / fmaxf(sqrtf(ssq[i]), 1e-12f);
            float4 raw = make_float4(v[i][0], v[i][1], v[i][2], v[i][3]);
            ((float4*)g_ego)[node * 16 + (c0 >> 2)] = raw;
            float4 nn = make_float4(raw.x * inv, raw.y * inv, raw.z * inv, raw.w * inv);
            ((float4*)g_final)[node * 64 + (layer + 1) * 16 + (c0 >> 2)] = nn;
        }
    }
}

// ---------------------------------------------------------------------------
// gather: out = [final[u] | final[nu+i] | final[nu+j]]
// ---------------------------------------------------------------------------
__global__ __launch_bounds__(256) void gather_kernel(const int* __restrict__ u,
                                                     const int* __restrict__ ii,
                                                     const int* __restrict__ jj,
                                                     int n_users, int B,
                                                     float4* __restrict__ out) {
    int idx = blockIdx.x * 256 + threadIdx.x;
    int total = 3 * B * 64;
    if (idx >= total) return;
    int c = idx & 63;
    int t = idx >> 6;
    int b = t % B;
    int sel = t / B;
    int row = (sel == 0) ? __ldg(u + b)
            : (sel == 1) ? (n_users + __ldg(ii + b))
                         : (n_users + __ldg(jj + b));
    out[idx] = ((const float4*)g_final)[row * 64 + c];
}

// ---------------------------------------------------------------------------
extern "C" void kernel_launch(void* const* d_in, const int* in_sizes, int n_in,
                              void* d_out, int out_size) {
    const float* user = (const float*)d_in[0];
    const float* item = (const float*)d_in[1];
    const float* Wgc  = (const float*)d_in[2];
    const float* bgc  = (const float*)d_in[3];
    const float* Wbi  = (const float*)d_in[4];
    const float* bbi  = (const float*)d_in[5];
    const float* vals = (const float*)d_in[6];
    const int*   rows = (const int*)d_in[7];
    const int*   cols = (const int*)d_in[8];
    const int*   u    = (const int*)d_in[9];
    const int*   ii   = (const int*)d_in[10];
    const int*   jj   = (const int*)d_in[11];

    int n_users = in_sizes[0] / D;
    int n_items = in_sizes[1] / D;
    int n = n_users + n_items;
    int nnz = in_sizes[6];
    int L = in_sizes[2] / (D * D);
    int B = in_sizes[9];

    cudaFuncSetAttribute(transform_kernel,
                         cudaFuncAttributeMaxDynamicSharedMemorySize, TSMEM);

    int eb = (nnz + 255) / 256;
    int nb = (n + 255) / 256;
    init_kernel<<<(n * 16 + 255) / 256, 256>>>((const float4*)user, (const float4*)item,
                                               n_users, n);
    count_kernel<<<eb, 256>>>(rows, nnz);
    scan1_kernel<<<nb, 256>>>(n);
    scan2_kernel<<<1, 1024>>>(nb);
    finalize_kernel<<<nb, 256>>>(n, nnz);
    scatter_kernel<<<eb, 256>>>(vals, rows, cols, nnz);

    for (int l = 0; l < L; l++) {
        spmm_csr_kernel<<<(n + 15) / 16, 256>>>(n);
        transform_kernel<<<(n + 63) / 64, 256, TSMEM>>>(
            (const float4*)(Wgc + l * D * D), bgc + l * D,
            (const float4*)(Wbi + l * D * D), bbi + l * D, n, l);
    }
    gather_kernel<<<(3 * B * 64 + 255) / 256, 256>>>(u, ii, jj, n_users, B, (float4*)d_out);
}

// round 6
// speedup vs baseline: 1.9747x; 1.0345x over previous
#include <cuda_runtime.h>
#include <cuda_fp16.h>

#define D 64
#define MAXN 150016
#define MAXNNZ 2500000
typedef unsigned long long ull;

// Scratch in device globals (no dynamic allocation allowed).
__device__ __align__(16) float  g_ego[MAXN * D];        // 38.4 MB f32 (transform)
__device__ __align__(16) __half g_egoh[MAXN * D];       // 19.2 MB fp16 shadow (spmm gather)
__device__ __align__(16) float  g_side[MAXN * D];       // 38.4 MB
__device__ __align__(16) float  g_final[MAXN * D * 4];  // 153.6 MB concat buffer
__device__ __align__(16) int2   g_edge[MAXNNZ];         // CSR (col, val) pairs
__device__ int g_hist[MAXN];
__device__ int g_rowptr[MAXN + 1];
__device__ int g_cursor[MAXN];
__device__ int g_partial[1024];

__device__ __forceinline__ float lrelu(float x) { return x >= 0.f ? x : 0.2f * x; }

__device__ __forceinline__ ull ffma2(ull a, ull b, ull c) {
    ull d;
    asm("fma.rn.f32x2 %0, %1, %2, %3;" : "=l"(d) : "l"(a), "l"(b), "l"(c));
    return d;
}

union f2u { float2 f; ull u; };
__device__ __forceinline__ ull pack2(float x, float y) { f2u t; t.f = make_float2(x, y); return t.u; }

// ---------------------------------------------------------------------------
// init: ego/egoh = concat(user,item); final[:,0:64] = ego; hist = 0
// (count is a SEPARATE kernel: zeroing must complete before edge atomics)
// ---------------------------------------------------------------------------
__global__ __launch_bounds__(256) void init_kernel(const float4* __restrict__ user,
                                                   const float4* __restrict__ item,
                                                   int n_users, int n_nodes) {
    int idx = blockIdx.x * 256 + threadIdx.x;
    if (idx >= n_nodes * 16) return;
    int n = idx >> 4, c = idx & 15;
    float4 v = (n < n_users) ? __ldg(user + n * 16 + c)
                             : __ldg(item + (n - n_users) * 16 + c);
    ((float4*)g_ego)[idx] = v;
    ((float4*)g_final)[n * 64 + c] = v;
    __half2 h0 = __floats2half2_rn(v.x, v.y);
    __half2 h1 = __floats2half2_rn(v.z, v.w);
    ((uint2*)g_egoh)[idx] = make_uint2(*(unsigned*)&h0, *(unsigned*)&h1);
    if (c == 0) g_hist[n] = 0;
}

__global__ __launch_bounds__(256) void count_kernel(const int* __restrict__ rows, int nnz) {
    int e = blockIdx.x * 256 + threadIdx.x;
    if (e < nnz) atomicAdd(&g_hist[__ldg(rows + e)], 1);
}

// ---------------------------------------------------------------------------
// CSR build: scan (3 stages) -> scatter
// ---------------------------------------------------------------------------
__global__ __launch_bounds__(256) void scan1_kernel(int n) {
    __shared__ int wsum[8];
    int i = blockIdx.x * 256 + threadIdx.x;
    int lane = threadIdx.x & 31, w = threadIdx.x >> 5;
    int v = (i < n) ? g_hist[i] : 0;
    int x = v;
#pragma unroll
    for (int off = 1; off < 32; off <<= 1) {
        int y = __shfl_up_sync(0xffffffffu, x, off);
        if (lane >= off) x += y;
    }
    if (lane == 31) wsum[w] = x;
    __syncthreads();
    if (threadIdx.x == 0) {
        int run = 0;
#pragma unroll
        for (int q = 0; q < 8; q++) { int t = wsum[q]; wsum[q] = run; run += t; }
        g_partial[blockIdx.x] = run;
    }
    __syncthreads();
    if (i < n) g_rowptr[i] = x - v + wsum[w];
}

__global__ __launch_bounds__(1024) void scan2_kernel(int nblocks) {
    __shared__ int sh[1024];
    int t = threadIdx.x;
    int v = (t < nblocks) ? g_partial[t] : 0;
    sh[t] = v;
    __syncthreads();
#pragma unroll
    for (int off = 1; off < 1024; off <<= 1) {
        int add = (t >= off) ? sh[t - off] : 0;
        __syncthreads();
        sh[t] += add;
        __syncthreads();
    }
    if (t < nblocks) g_partial[t] = sh[t] - v;  // exclusive
}

__global__ __launch_bounds__(256) void finalize_kernel(int n, int nnz) {
    int i = blockIdx.x * 256 + threadIdx.x;
    if (i < n) {
        int off = g_rowptr[i] + g_partial[i >> 8];
        g_rowptr[i] = off;
        g_cursor[i] = off;
    }
    if (i == 0) g_rowptr[n] = nnz;
}

__global__ __launch_bounds__(256) void scatter_kernel(const float* __restrict__ vals,
                                                      const int* __restrict__ rows,
                                                      const int* __restrict__ cols,
                                                      int nnz) {
    int e = blockIdx.x * 256 + threadIdx.x;
    if (e >= nnz) return;
    int r = __ldg(rows + e);
    int pos = atomicAdd(&g_cursor[r], 1);
    g_edge[pos] = make_int2(__ldg(cols + e), __float_as_int(__ldg(vals + e)));
}

// ---------------------------------------------------------------------------
// spmm: gather from fp16 shadow (128B/row), accumulate f32.
// 8 threads per row (32 rows / 256-thread block), each thread owns 8 dims
// (one uint4 = 8 halves), 4 edges in flight, f32x2 accumulate.
// ---------------------------------------------------------------------------
__global__ __launch_bounds__(256) void spmm_csr_kernel(int n) {
    int row = blockIdx.x * 32 + (threadIdx.x >> 3);
    if (row >= n) return;
    int c = threadIdx.x & 7;
    int s = __ldg(&g_rowptr[row]);
    int e = __ldg(&g_rowptr[row + 1]);
    const uint4* __restrict__ egoh = (const uint4*)g_egoh;  // 8 uint4 per row

    ull A[4] = {0, 0, 0, 0};   // 8 f32 accumulators as f32x2 pairs
    ull B[4] = {0, 0, 0, 0};

    int p = s;
    for (; p + 4 <= e; p += 4) {
        int2 e0 = __ldg(&g_edge[p]);
        int2 e1 = __ldg(&g_edge[p + 1]);
        int2 e2 = __ldg(&g_edge[p + 2]);
        int2 e3 = __ldg(&g_edge[p + 3]);
        uint4 x0 = __ldg(egoh + e0.x * 8 + c);
        uint4 x1 = __ldg(egoh + e1.x * 8 + c);
        uint4 x2 = __ldg(egoh + e2.x * 8 + c);
        uint4 x3 = __ldg(egoh + e3.x * 8 + c);
        float v0 = __int_as_float(e0.y), v1 = __int_as_float(e1.y);
        float v2 = __int_as_float(e2.y), v3 = __int_as_float(e3.y);
        ull vv0 = pack2(v0, v0), vv1 = pack2(v1, v1);
        ull vv2 = pack2(v2, v2), vv3 = pack2(v3, v3);
        {
            f2u f;
            f.f = __half22float2(*(__half2*)&x0.x); A[0] = ffma2(vv0, f.u, A[0]);
            f.f = __half22float2(*(__half2*)&x0.y); A[1] = ffma2(vv0, f.u, A[1]);
            f.f = __half22float2(*(__half2*)&x0.z); A[2] = ffma2(vv0, f.u, A[2]);
            f.f = __half22float2(*(__half2*)&x0.w); A[3] = ffma2(vv0, f.u, A[3]);
            f.f = __half22float2(*(__half2*)&x1.x); B[0] = ffma2(vv1, f.u, B[0]);
            f.f = __half22float2(*(__half2*)&x1.y); B[1] = ffma2(vv1, f.u, B[1]);
            f.f = __half22float2(*(__half2*)&x1.z); B[2] = ffma2(vv1, f.u, B[2]);
            f.f = __half22float2(*(__half2*)&x1.w); B[3] = ffma2(vv1, f.u, B[3]);
            f.f = __half22float2(*(__half2*)&x2.x); A[0] = ffma2(vv2, f.u, A[0]);
            f.f = __half22float2(*(__half2*)&x2.y); A[1] = ffma2(vv2, f.u, A[1]);
            f.f = __half22float2(*(__half2*)&x2.z); A[2] = ffma2(vv2, f.u, A[2]);
            f.f = __half22float2(*(__half2*)&x2.w); A[3] = ffma2(vv2, f.u, A[3]);
            f.f = __half22float2(*(__half2*)&x3.x); B[0] = ffma2(vv3, f.u, B[0]);
            f.f = __half22float2(*(__half2*)&x3.y); B[1] = ffma2(vv3, f.u, B[1]);
            f.f = __half22float2(*(__half2*)&x3.z); B[2] = ffma2(vv3, f.u, B[2]);
            f.f = __half22float2(*(__half2*)&x3.w); B[3] = ffma2(vv3, f.u, B[3]);
        }
    }
    for (; p < e; p++) {
        int2 ed = __ldg(&g_edge[p]);
        uint4 x = __ldg(egoh + ed.x * 8 + c);
        float v = __int_as_float(ed.y);
        ull vv = pack2(v, v);
        f2u f;
        f.f = __half22float2(*(__half2*)&x.x); A[0] = ffma2(vv, f.u, A[0]);
        f.f = __half22float2(*(__half2*)&x.y); A[1] = ffma2(vv, f.u, A[1]);
        f.f = __half22float2(*(__half2*)&x.z); A[2] = ffma2(vv, f.u, A[2]);
        f.f = __half22float2(*(__half2*)&x.w); A[3] = ffma2(vv, f.u, A[3]);
    }

    float4 o0, o1;
    { f2u a, b;
      a.u = A[0]; b.u = B[0]; o0.x = a.f.x + b.f.x; o0.y = a.f.y + b.f.y;
      a.u = A[1]; b.u = B[1]; o0.z = a.f.x + b.f.x; o0.w = a.f.y + b.f.y;
      a.u = A[2]; b.u = B[2]; o1.x = a.f.x + b.f.x; o1.y = a.f.y + b.f.y;
      a.u = A[3]; b.u = B[3]; o1.z = a.f.x + b.f.x; o1.w = a.f.y + b.f.y; }
    float4* dst = (float4*)g_side + row * 16 + c * 2;
    dst[0] = o0;
    dst[1] = o1;
}

// ---------------------------------------------------------------------------
// transform: ego_new = lrelu(side@Wgc+bg) + lrelu((ego*side)@Wbi+bb)
//            g_final slice = normalize(ego_new);  ego/egoh <- ego_new (raw)
// 64-node tile, 256 threads, 4x4 per thread, f32x2 packed FMA.
// ---------------------------------------------------------------------------
#define RPITCH 66  // float2 units per k-row (even => 16B alignment at even k)
#define TSMEM (2 * 64 * RPITCH * 8 + 2 * 4096 * 4)  // 100352 bytes

__global__ __launch_bounds__(256, 2) void transform_kernel(const float4* __restrict__ Wgc,
                                                           const float* __restrict__ bgc,
                                                           const float4* __restrict__ Wbi,
                                                           const float* __restrict__ bbi,
                                                           int n_nodes, int layer) {
    extern __shared__ char shraw[];
    float2* SD = (float2*)shraw;               // [64 rows][64 k] duplicated (s,s)
    float2* PD = SD + 64 * RPITCH;             // duplicated (p,p)
    float*  Wg = (float*)(PD + 64 * RPITCH);   // [64 k][64 c]
    float*  Wb = Wg + 4096;

    int tid = threadIdx.x;
    int base = blockIdx.x * 64;

    for (int i = tid; i < 1024; i += 256) {
        ((float4*)Wg)[i] = __ldg(Wgc + i);
        ((float4*)Wb)[i] = __ldg(Wbi + i);
        int r = i >> 4, cc = i & 15;
        int node = base + r;
        float4 s4 = make_float4(0.f, 0.f, 0.f, 0.f);
        float4 e4 = s4;
        if (node < n_nodes) {
            s4 = ((const float4*)g_side)[node * 16 + cc];
            e4 = ((const float4*)g_ego)[node * 16 + cc];
        }
        int kb = cc * 4;
        float2* sd = &SD[r * RPITCH + kb];
        float2* pd = &PD[r * RPITCH + kb];
        sd[0] = make_float2(s4.x, s4.x);
        sd[1] = make_float2(s4.y, s4.y);
        sd[2] = make_float2(s4.z, s4.z);
        sd[3] = make_float2(s4.w, s4.w);
        pd[0] = make_float2(s4.x * e4.x, s4.x * e4.x);
        pd[1] = make_float2(s4.y * e4.y, s4.y * e4.y);
        pd[2] = make_float2(s4.z * e4.z, s4.z * e4.z);
        pd[3] = make_float2(s4.w * e4.w, s4.w * e4.w);
    }
    __syncthreads();

    int r0 = (tid >> 4) * 4;   // node sub-rows
    int c0 = (tid & 15) * 4;   // output cols

    ull ag[4][2] = {}, ab[4][2] = {};

#pragma unroll 4
    for (int k = 0; k < 64; k += 2) {
        ulonglong2 wg0 = *(const ulonglong2*)&Wg[k * 64 + c0];
        ulonglong2 wg1 = *(const ulonglong2*)&Wg[(k + 1) * 64 + c0];
        ulonglong2 wb0 = *(const ulonglong2*)&Wb[k * 64 + c0];
        ulonglong2 wb1 = *(const ulonglong2*)&Wb[(k + 1) * 64 + c0];
#pragma unroll
        for (int i = 0; i < 4; i++) {
            ulonglong2 sd = *(const ulonglong2*)&SD[(r0 + i) * RPITCH + k];
            ulonglong2 pd = *(const ulonglong2*)&PD[(r0 + i) * RPITCH + k];
            ag[i][0] = ffma2(sd.x, wg0.x, ag[i][0]);
            ag[i][1] = ffma2(sd.x, wg0.y, ag[i][1]);
            ag[i][0] = ffma2(sd.y, wg1.x, ag[i][0]);
            ag[i][1] = ffma2(sd.y, wg1.y, ag[i][1]);
            ab[i][0] = ffma2(pd.x, wb0.x, ab[i][0]);
            ab[i][1] = ffma2(pd.x, wb0.y, ab[i][1]);
            ab[i][0] = ffma2(pd.y, wb1.x, ab[i][0]);
            ab[i][1] = ffma2(pd.y, wb1.y, ab[i][1]);
        }
    }

    float4 bg4 = __ldg((const float4*)bgc + (c0 >> 2));
    float4 bb4 = __ldg((const float4*)bbi + (c0 >> 2));

    float v[4][4];
    float ssq[4];
#pragma unroll
    for (int i = 0; i < 4; i++) {
        f2u a0, a1, b0, b1;
        a0.u = ag[i][0]; a1.u = ag[i][1];
        b0.u = ab[i][0]; b1.u = ab[i][1];
        v[i][0] = lrelu(a0.f.x + bg4.x) + lrelu(b0.f.x + bb4.x);
        v[i][1] = lrelu(a0.f.y + bg4.y) + lrelu(b0.f.y + bb4.y);
        v[i][2] = lrelu(a1.f.x + bg4.z) + lrelu(b1.f.x + bb4.z);
        v[i][3] = lrelu(a1.f.y + bg4.w) + lrelu(b1.f.y + bb4.w);
        ssq[i] = v[i][0] * v[i][0] + v[i][1] * v[i][1] + v[i][2] * v[i][2] + v[i][3] * v[i][3];
    }
    // reduce ssq across the 16 threads (lanes tid&15) sharing the same rows
#pragma unroll
    for (int off = 1; off < 16; off <<= 1) {
#pragma unroll
        for (int i = 0; i < 4; i++)
            ssq[i] += __shfl_xor_sync(0xffffffffu, ssq[i], off);
    }
#pragma unroll
    for (int i = 0; i < 4; i++) {
        int node = base + r0 + i;
        if (node < n_nodes) {
            float inv = 1.0f / fmaxf(sqrtf(ssq[i]), 1e-12f);
            float4 raw = make_float4(v[i][0], v[i][1], v[i][2], v[i][3]);
            ((float4*)g_ego)[node * 16 + (c0 >> 2)] = raw;  // raw carries forward
            __half2 h0 = __floats2half2_rn(raw.x, raw.y);
            __half2 h1 = __floats2half2_rn(raw.z, raw.w);
            ((uint*)g_egoh)[node * 32 + (c0 >> 1)]     = *(unsigned*)&h0;
            ((uint*)g_egoh)[node * 32 + (c0 >> 1) + 1] = *(unsigned*)&h1;
            float4 nn = make_float4(raw.x * inv, raw.y * inv, raw.z * inv, raw.w * inv);
            ((float4*)g_final)[node * 64 + (layer + 1) * 16 + (c0 >> 2)] = nn;
        }
    }
}

// ---------------------------------------------------------------------------
// gather: out = [final[u] | final[nu+i] | final[nu+j]]
// ---------------------------------------------------------------------------
__global__ __launch_bounds__(256) void gather_kernel(const int* __restrict__ u,
                                                     const int* __restrict__ ii,
                                                     const int* __restrict__ jj,
                                                     int n_users, int B,
                                                     float4* __restrict__ out) {
    int idx = blockIdx.x * 256 + threadIdx.x;
    int total = 3 * B * 64;
    if (idx >= total) return;
    int c = idx & 63;
    int t = idx >> 6;
    int b = t % B;
    int sel = t / B;
    int row = (sel == 0) ? __ldg(u + b)
            : (sel == 1) ? (n_users + __ldg(ii + b))
                         : (n_users + __ldg(jj + b));
    out[idx] = ((const float4*)g_final)[row * 64 + c];
}

// ---------------------------------------------------------------------------
extern "C" void kernel_launch(void* const* d_in, const int* in_sizes, int n_in,
                              void* d_out, int out_size) {
    const float* user = (const float*)d_in[0];
    const float* item = (const float*)d_in[1];
    const float* Wgc  = (const float*)d_in[2];
    const float* bgc  = (const float*)d_in[3];
    const float* Wbi  = (const float*)d_in[4];
    const float* bbi  = (const float*)d_in[5];
    const float* vals = (const float*)d_in[6];
    const int*   rows = (const int*)d_in[7];
    const int*   cols = (const int*)d_in[8];
    const int*   u    = (const int*)d_in[9];
    const int*   ii   = (const int*)d_in[10];
    const int*   jj   = (const int*)d_in[11];

    int n_users = in_sizes[0] / D;
    int n_items = in_sizes[1] / D;
    int n = n_users + n_items;
    int nnz = in_sizes[6];
    int L = in_sizes[2] / (D * D);
    int B = in_sizes[9];

    cudaFuncSetAttribute(transform_kernel,
                         cudaFuncAttributeMaxDynamicSharedMemorySize, TSMEM);

    int eb = (nnz + 255) / 256;
    int nb = (n + 255) / 256;
    init_kernel<<<(n * 16 + 255) / 256, 256>>>((const float4*)user, (const float4*)item,
                                               n_users, n);
    count_kernel<<<eb, 256>>>(rows, nnz);
    scan1_kernel<<<nb, 256>>>(n);
    scan2_kernel<<<1, 1024>>>(nb);
    finalize_kernel<<<nb, 256>>>(n, nnz);
    scatter_kernel<<<eb, 256>>>(vals, rows, cols, nnz);

    for (int l = 0; l < L; l++) {
        spmm_csr_kernel<<<(n + 31) / 32, 256>>>(n);
        transform_kernel<<<(n + 63) / 64, 256, TSMEM>>>(
            (const float4*)(Wgc + l * D * D), bgc + l * D,
            (const float4*)(Wbi + l * D * D), bbi + l * D, n, l);
    }
    gather_kernel<<<(3 * B * 64 + 255) / 256, 256>>>(u, ii, jj, n_users, B, (float4*)d_out);
}

// round 8
// speedup vs baseline: 2.2488x; 1.1388x over previous
#include <cuda_runtime.h>
#include <cuda_fp16.h>
#include <mma.h>
#include <cstdint>

using namespace nvcuda;

#define D 64
#define MAXN 150016
#define MAXNNZ 2500000

// Scratch in device globals (no dynamic allocation allowed).
__device__ __align__(16) __half g_egoh[MAXN * D];       // 19.2 MB fp16 carried state
__device__ __align__(16) __half g_sideh[MAXN * D];      // 19.2 MB spmm output
__device__ __align__(16) __half g_prodh[MAXN * D];      // 19.2 MB side*ego
__device__ __align__(16) float  g_final[MAXN * D * 4];  // 153.6 MB concat buffer
__device__ __align__(16) int2   g_edge[MAXNNZ];         // CSR (col, val) pairs
__device__ __align__(16) __half g_Wh[3 * 2 * 4096];     // fp16 weights [l][gc/bi][k][n]
__device__ int g_hist[MAXN];
__device__ int g_rowptr[MAXN + 1];
__device__ int g_rank[MAXNNZ];
__device__ int g_partial[1024];

__device__ __forceinline__ float lrelu(float x) { return x >= 0.f ? x : 0.2f * x; }

// ---------------------------------------------------------------------------
// init: egoh = fp16(concat(user,item)); final[:,0:64] = f32; hist = 0
// ---------------------------------------------------------------------------
__global__ __launch_bounds__(256) void init_kernel(const float4* __restrict__ user,
                                                   const float4* __restrict__ item,
                                                   int n_users, int n_nodes) {
    int idx = blockIdx.x * 256 + threadIdx.x;
    if (idx >= n_nodes * 16) return;
    int n = idx >> 4, c = idx & 15;
    float4 v = (n < n_users) ? __ldg(user + n * 16 + c)
                             : __ldg(item + (n - n_users) * 16 + c);
    ((float4*)g_final)[n * 64 + c] = v;
    __half2 h0 = __floats2half2_rn(v.x, v.y);
    __half2 h1 = __floats2half2_rn(v.z, v.w);
    ((uint2*)g_egoh)[idx] = make_uint2(*(uint32_t*)&h0, *(uint32_t*)&h1);
    if (c == 0) g_hist[n] = 0;
}

// W prep: plain f32 -> fp16 convert, layout preserved ([k][n] row-major)
__global__ __launch_bounds__(256) void wprep_kernel(const float* __restrict__ Wgc,
                                                    const float* __restrict__ Wbi,
                                                    int L) {
    int idx = blockIdx.x * 256 + threadIdx.x;
    if (idx >= L * 8192) return;
    int l = idx >> 13;
    int r = idx & 8191;
    int mtx = r >> 12;
    int pos = r & 4095;
    const float* W = mtx ? Wbi : Wgc;
    g_Wh[idx] = __float2half(W[l * 4096 + pos]);
}

// ---------------------------------------------------------------------------
// CSR build: count (records rank) -> scan -> scatter (no atomics in scatter)
// ---------------------------------------------------------------------------
__global__ __launch_bounds__(256) void count_kernel(const int* __restrict__ rows, int nnz) {
    int e = blockIdx.x * 256 + threadIdx.x;
    if (e < nnz) g_rank[e] = atomicAdd(&g_hist[__ldg(rows + e)], 1);
}

__global__ __launch_bounds__(256) void scan1_kernel(int n) {
    __shared__ int wsum[8];
    int i = blockIdx.x * 256 + threadIdx.x;
    int lane = threadIdx.x & 31, w = threadIdx.x >> 5;
    int v = (i < n) ? g_hist[i] : 0;
    int x = v;
#pragma unroll
    for (int off = 1; off < 32; off <<= 1) {
        int y = __shfl_up_sync(0xffffffffu, x, off);
        if (lane >= off) x += y;
    }
    if (lane == 31) wsum[w] = x;
    __syncthreads();
    if (threadIdx.x == 0) {
        int run = 0;
#pragma unroll
        for (int q = 0; q < 8; q++) { int t = wsum[q]; wsum[q] = run; run += t; }
        g_partial[blockIdx.x] = run;
    }
    __syncthreads();
    if (i < n) g_rowptr[i] = x - v + wsum[w];
}

__global__ __launch_bounds__(1024) void scan2_kernel(int nblocks) {
    __shared__ int sh[1024];
    int t = threadIdx.x;
    int v = (t < nblocks) ? g_partial[t] : 0;
    sh[t] = v;
    __syncthreads();
#pragma unroll
    for (int off = 1; off < 1024; off <<= 1) {
        int add = (t >= off) ? sh[t - off] : 0;
        __syncthreads();
        sh[t] += add;
        __syncthreads();
    }
    if (t < nblocks) g_partial[t] = sh[t] - v;  // exclusive
}

__global__ __launch_bounds__(256) void finalize_kernel(int n, int nnz) {
    int i = blockIdx.x * 256 + threadIdx.x;
    if (i < n) g_rowptr[i] += g_partial[i >> 8];
    if (i == 0) g_rowptr[n] = nnz;
}

__global__ __launch_bounds__(256) void scatter_kernel(const float* __restrict__ vals,
                                                      const int* __restrict__ rows,
                                                      const int* __restrict__ cols,
                                                      int nnz) {
    int e = blockIdx.x * 256 + threadIdx.x;
    if (e >= nnz) return;
    int r = __ldg(rows + e);
    int pos = __ldg(&g_rowptr[r]) + g_rank[e];
    g_edge[pos] = make_int2(__ldg(cols + e), __float_as_int(__ldg(vals + e)));
}

// ---------------------------------------------------------------------------
// spmm: gather fp16 rows (128B line each), f32 accumulate, write side_h and
// prod_h = side*ego (fp16). 8 threads/row, 4 edges in flight.
// ---------------------------------------------------------------------------
__device__ __forceinline__ void acc8(float* o, uint4 x, float v) {
    float2 f;
    f = __half22float2(*(__half2*)&x.x); o[0] += v * f.x; o[1] += v * f.y;
    f = __half22float2(*(__half2*)&x.y); o[2] += v * f.x; o[3] += v * f.y;
    f = __half22float2(*(__half2*)&x.z); o[4] += v * f.x; o[5] += v * f.y;
    f = __half22float2(*(__half2*)&x.w); o[6] += v * f.x; o[7] += v * f.y;
}

__global__ __launch_bounds__(256) void spmm_csr_kernel(int n) {
    int row = blockIdx.x * 32 + (threadIdx.x >> 3);
    if (row >= n) return;
    int c = threadIdx.x & 7;
    int s = __ldg(&g_rowptr[row]);
    int e = __ldg(&g_rowptr[row + 1]);
    const uint4* __restrict__ egoh = (const uint4*)g_egoh;  // 8 uint4 per row

    float oA[8] = {0, 0, 0, 0, 0, 0, 0, 0};
    float oB[8] = {0, 0, 0, 0, 0, 0, 0, 0};
    int p = s;
    for (; p + 4 <= e; p += 4) {
        int2 e0 = __ldg(&g_edge[p]);
        int2 e1 = __ldg(&g_edge[p + 1]);
        int2 e2 = __ldg(&g_edge[p + 2]);
        int2 e3 = __ldg(&g_edge[p + 3]);
        uint4 x0 = __ldg(egoh + e0.x * 8 + c);
        uint4 x1 = __ldg(egoh + e1.x * 8 + c);
        uint4 x2 = __ldg(egoh + e2.x * 8 + c);
        uint4 x3 = __ldg(egoh + e3.x * 8 + c);
        acc8(oA, x0, __int_as_float(e0.y));
        acc8(oB, x1, __int_as_float(e1.y));
        acc8(oA, x2, __int_as_float(e2.y));
        acc8(oB, x3, __int_as_float(e3.y));
    }
    for (; p < e; p++) {
        int2 ed = __ldg(&g_edge[p]);
        uint4 x = __ldg(egoh + ed.x * 8 + c);
        acc8(oA, x, __int_as_float(ed.y));
    }
#pragma unroll
    for (int j = 0; j < 8; j++) oA[j] += oB[j];

    // self term for bi-interaction
    uint4 sh = __ldg(egoh + row * 8 + c);
    float self[8];
    { float2 f;
      f = __half22float2(*(__half2*)&sh.x); self[0] = f.x; self[1] = f.y;
      f = __half22float2(*(__half2*)&sh.y); self[2] = f.x; self[3] = f.y;
      f = __half22float2(*(__half2*)&sh.z); self[4] = f.x; self[5] = f.y;
      f = __half22float2(*(__half2*)&sh.w); self[6] = f.x; self[7] = f.y; }

    uint4 us, up;
    { __half2 h0 = __floats2half2_rn(oA[0], oA[1]);
      __half2 h1 = __floats2half2_rn(oA[2], oA[3]);
      __half2 h2 = __floats2half2_rn(oA[4], oA[5]);
      __half2 h3 = __floats2half2_rn(oA[6], oA[7]);
      us.x = *(uint32_t*)&h0; us.y = *(uint32_t*)&h1;
      us.z = *(uint32_t*)&h2; us.w = *(uint32_t*)&h3; }
    { __half2 h0 = __floats2half2_rn(oA[0] * self[0], oA[1] * self[1]);
      __half2 h1 = __floats2half2_rn(oA[2] * self[2], oA[3] * self[3]);
      __half2 h2 = __floats2half2_rn(oA[4] * self[4], oA[5] * self[5]);
      __half2 h3 = __floats2half2_rn(oA[6] * self[6], oA[7] * self[7]);
      up.x = *(uint32_t*)&h0; up.y = *(uint32_t*)&h1;
      up.z = *(uint32_t*)&h2; up.w = *(uint32_t*)&h3; }
    ((uint4*)g_sideh)[row * 8 + c] = us;
    ((uint4*)g_prodh)[row * 8 + c] = up;
}

// ---------------------------------------------------------------------------
// transform via wmma (HMMA, fp16 in / f32 accum): per 128-row tile,
//   Dg = S @ Wg,  Db = P @ Wb  (S,P: [128x64] fp16; W: [64x64] fp16 row-major)
// epilogue: v = lrelu(Dg+bg)+lrelu(Db+bb); egoh <- fp16(v); final <- v/||v||
// smem: input phase (S,P,Wg,Wb) then C phase (Cg,Cb f32, reuses same region).
// ---------------------------------------------------------------------------
#define SM_BG 0
#define SM_BB 256
#define SM_S  512
#define SM_P  (SM_S + 128 * 64 * 2)            // 16896
#define SM_WG (SM_P + 128 * 64 * 2)            // 33280
#define SM_WB (SM_WG + 64 * 64 * 2)            // 41472
#define CPITCH 68
#define SM_CG 512
#define SM_CB (SM_CG + 128 * CPITCH * 4)       // 35328
#define WSMEM (SM_CB + 128 * CPITCH * 4)       // 70144 bytes

__global__ __launch_bounds__(256) void wmma_transform_kernel(const float* __restrict__ bgc,
                                                             const float* __restrict__ bbi,
                                                             int n, int layer) {
    extern __shared__ char sm[];
    __half* Sh = (__half*)(sm + SM_S);
    __half* Ph = (__half*)(sm + SM_P);
    __half* Wg = (__half*)(sm + SM_WG);
    __half* Wb = (__half*)(sm + SM_WB);
    float*  BG = (float*)(sm + SM_BG);
    float*  BB = (float*)(sm + SM_BB);
    float*  Cg = (float*)(sm + SM_CG);
    float*  Cb = (float*)(sm + SM_CB);

    int tid = threadIdx.x;
    int base = blockIdx.x * 128;

    // load S/P tiles: 128 rows x 8 uint4
    const uint4* Sg4 = (const uint4*)g_sideh;
    const uint4* Pg4 = (const uint4*)g_prodh;
    for (int i = tid; i < 1024; i += 256) {
        int r = i >> 3;
        int node = base + r;
        uint4 sv = make_uint4(0, 0, 0, 0), pv = sv;
        if (node < n) {
            sv = __ldg(Sg4 + node * 8 + (i & 7));
            pv = __ldg(Pg4 + node * 8 + (i & 7));
        }
        ((uint4*)Sh)[i] = sv;
        ((uint4*)Ph)[i] = pv;
    }
    const uint4* wg4 = (const uint4*)(g_Wh + layer * 8192);
    const uint4* wb4 = wg4 + 512;
    for (int i = tid; i < 512; i += 256) {
        ((uint4*)Wg)[i] = __ldg(wg4 + i);
        ((uint4*)Wb)[i] = __ldg(wb4 + i);
    }
    if (tid < 64) { BG[tid] = __ldg(bgc + tid); BB[tid] = __ldg(bbi + tid); }
    __syncthreads();

    // each warp computes rows [16w, 16w+16) x all 64 cols, both GEMMs
    int w = tid >> 5;
    wmma::fragment<wmma::accumulator, 16, 16, 16, float> accg[4], accb[4];
#pragma unroll
    for (int t = 0; t < 4; t++) {
        wmma::fill_fragment(accg[t], 0.f);
        wmma::fill_fragment(accb[t], 0.f);
    }
#pragma unroll
    for (int k = 0; k < 64; k += 16) {
        wmma::fragment<wmma::matrix_a, 16, 16, 16, __half, wmma::row_major> aS, aP;
        wmma::load_matrix_sync(aS, Sh + (w * 16) * 64 + k, 64);
        wmma::load_matrix_sync(aP, Ph + (w * 16) * 64 + k, 64);
#pragma unroll
        for (int t = 0; t < 4; t++) {
            wmma::fragment<wmma::matrix_b, 16, 16, 16, __half, wmma::row_major> bG, bB;
            wmma::load_matrix_sync(bG, Wg + k * 64 + t * 16, 64);
            wmma::load_matrix_sync(bB, Wb + k * 64 + t * 16, 64);
            wmma::mma_sync(accg[t], aS, bG, accg[t]);
            wmma::mma_sync(accb[t], aP, bB, accb[t]);
        }
    }
    __syncthreads();  // everyone done reading S/P/W before C overwrites
#pragma unroll
    for (int t = 0; t < 4; t++) {
        wmma::store_matrix_sync(Cg + (w * 16) * CPITCH + t * 16, accg[t], CPITCH,
                                wmma::mem_row_major);
        wmma::store_matrix_sync(Cb + (w * 16) * CPITCH + t * 16, accb[t], CPITCH,
                                wmma::mem_row_major);
    }
    __syncthreads();

    // epilogue: thread pair per row; t&1 selects col half [32h, 32h+32)
    int r = tid >> 1, h = tid & 1;
    int node = base + r;
    float v[32];
    float ssq = 0.f;
    const float4* cg4 = (const float4*)(Cg + r * CPITCH + h * 32);
    const float4* cb4 = (const float4*)(Cb + r * CPITCH + h * 32);
    const float4* bg4 = (const float4*)(BG + h * 32);
    const float4* bb4 = (const float4*)(BB + h * 32);
#pragma unroll
    for (int q = 0; q < 8; q++) {
        float4 a = cg4[q], b = cb4[q], ga = bg4[q], gb = bb4[q];
        v[4 * q + 0] = lrelu(a.x + ga.x) + lrelu(b.x + gb.x);
        v[4 * q + 1] = lrelu(a.y + ga.y) + lrelu(b.y + gb.y);
        v[4 * q + 2] = lrelu(a.z + ga.z) + lrelu(b.z + gb.z);
        v[4 * q + 3] = lrelu(a.w + ga.w) + lrelu(b.w + gb.w);
        ssq += v[4 * q] * v[4 * q] + v[4 * q + 1] * v[4 * q + 1]
             + v[4 * q + 2] * v[4 * q + 2] + v[4 * q + 3] * v[4 * q + 3];
    }
    ssq += __shfl_xor_sync(0xffffffffu, ssq, 1);

    if (node < n) {
        float inv = 1.0f / fmaxf(sqrtf(ssq), 1e-12f);
        uint4* eh = (uint4*)g_egoh + node * 8 + h * 4;
#pragma unroll
        for (int j = 0; j < 4; j++) {
            __half2 h0 = __floats2half2_rn(v[8 * j + 0], v[8 * j + 1]);
            __half2 h1 = __floats2half2_rn(v[8 * j + 2], v[8 * j + 3]);
            __half2 h2 = __floats2half2_rn(v[8 * j + 4], v[8 * j + 5]);
            __half2 h3 = __floats2half2_rn(v[8 * j + 6], v[8 * j + 7]);
            uint4 u;
            u.x = *(uint32_t*)&h0; u.y = *(uint32_t*)&h1;
            u.z = *(uint32_t*)&h2; u.w = *(uint32_t*)&h3;
            eh[j] = u;
        }
        float4* fo = (float4*)g_final + node * 64 + (layer + 1) * 16 + h * 8;
#pragma unroll
        for (int q = 0; q < 8; q++)
            fo[q] = make_float4(v[4 * q] * inv, v[4 * q + 1] * inv,
                                v[4 * q + 2] * inv, v[4 * q + 3] * inv);
    }
}

// ---------------------------------------------------------------------------
// gather: out = [final[u] | final[nu+i] | final[nu+j]]
// ---------------------------------------------------------------------------
__global__ __launch_bounds__(256) void gather_kernel(const int* __restrict__ u,
                                                     const int* __restrict__ ii,
                                                     const int* __restrict__ jj,
                                                     int n_users, int B,
                                                     float4* __restrict__ out) {
    int idx = blockIdx.x * 256 + threadIdx.x;
    int total = 3 * B * 64;
    if (idx >= total) return;
    int c = idx & 63;
    int t = idx >> 6;
    int b = t % B;
    int sel = t / B;
    int row = (sel == 0) ? __ldg(u + b)
            : (sel == 1) ? (n_users + __ldg(ii + b))
                         : (n_users + __ldg(jj + b));
    out[idx] = ((const float4*)g_final)[row * 64 + c];
}

// ---------------------------------------------------------------------------
extern "C" void kernel_launch(void* const* d_in, const int* in_sizes, int n_in,
                              void* d_out, int out_size) {
    const float* user = (const float*)d_in[0];
    const float* item = (const float*)d_in[1];
    const float* Wgc  = (const float*)d_in[2];
    const float* bgc  = (const float*)d_in[3];
    const float* Wbi  = (const float*)d_in[4];
    const float* bbi  = (const float*)d_in[5];
    const float* vals = (const float*)d_in[6];
    const int*   rows = (const int*)d_in[7];
    const int*   cols = (const int*)d_in[8];
    const int*   u    = (const int*)d_in[9];
    const int*   ii   = (const int*)d_in[10];
    const int*   jj   = (const int*)d_in[11];

    int n_users = in_sizes[0] / D;
    int n_items = in_sizes[1] / D;
    int n = n_users + n_items;
    int nnz = in_sizes[6];
    int L = in_sizes[2] / (D * D);
    int B = in_sizes[9];

    cudaFuncSetAttribute(wmma_transform_kernel,
                         cudaFuncAttributeMaxDynamicSharedMemorySize, WSMEM);

    int eb = (nnz + 255) / 256;
    int nb = (n + 255) / 256;
    init_kernel<<<(n * 16 + 255) / 256, 256>>>((const float4*)user, (const float4*)item,
                                               n_users, n);
    wprep_kernel<<<(L * 8192 + 255) / 256, 256>>>(Wgc, Wbi, L);
    count_kernel<<<eb, 256>>>(rows, nnz);
    scan1_kernel<<<nb, 256>>>(n);
    scan2_kernel<<<1, 1024>>>(nb);
    finalize_kernel<<<nb, 256>>>(n, nnz);
    scatter_kernel<<<eb, 256>>>(vals, rows, cols, nnz);

    for (int l = 0; l < L; l++) {
        spmm_csr_kernel<<<(n + 31) / 32, 256>>>(n);
        wmma_transform_kernel<<<(n + 127) / 128, 256, WSMEM>>>(
            bgc + l * D, bbi + l * D, n, l);
    }
    gather_kernel<<<(3 * B * 64 + 255) / 256, 256>>>(u, ii, jj, n_users, B, (float4*)d_out);
}